// round 2
// baseline (speedup 1.0000x reference)
#include <cuda_runtime.h>
#include <cstdint>

#define Hh   128
#define Ww   128
#define HW   16384
#define Cc   128
#define NP   9
#define OUTC 256
#define Bb   4
#define BPIX 32

// -------- device scratch (no allocations allowed) --------
__device__ float g_offset[Bb * 2 * NP * HW];   // (b, 18, H, W)
__device__ float g_wt[NP * Cc * OUTC];         // [n][c][o]

// ======================================================================
// Kernel 1: transpose w_conv (outc, C, N, 1) -> wt[n][c][o]
// ======================================================================
__global__ void wtrans_k(const float* __restrict__ wc) {
    int i = blockIdx.x * 256 + threadIdx.x;      // 0 .. 9*128*256-1
    if (i < NP * Cc * OUTC) {
        int o = i % OUTC;
        int r = i / OUTC;
        int c = r % Cc;
        int n = r / Cc;
        g_wt[i] = wc[(o * Cc + c) * NP + n];
    }
}

// ======================================================================
// Kernel 2: offset conv: x (b,C,H,W) * w_p (18,C,3,3) pad 1 stride 1
// Each block: one batch, two rows. 128 threads (one x-column each,
// two rows per thread).
// ======================================================================
__global__ void __launch_bounds__(128) offset_conv_k(
    const float* __restrict__ x,
    const float* __restrict__ wp,
    const float* __restrict__ bp)
{
    const int y0 = blockIdx.x * 2;
    const int b  = blockIdx.y;
    const int tx = threadIdx.x;

    __shared__ float xr[4][132];
    __shared__ float ws[168];

    float acc0[18];
    float acc1[18];
#pragma unroll
    for (int ch = 0; ch < 18; ch++) { acc0[ch] = 0.f; acc1[ch] = 0.f; }

    const float* xb = x + (size_t)b * Cc * HW;

    for (int c = 0; c < Cc; c++) {
        __syncthreads();
        // weights for this input channel: 18*9 = 162 floats
        for (int i = tx; i < 162; i += 128) {
            ws[i] = wp[(i / 9) * (Cc * 9) + c * 9 + (i % 9)];
        }
        // x rows y0-1 .. y0+2, cols -1 .. 128 (zero pad)
        for (int i = tx; i < 4 * 132; i += 128) {
            int r  = i / 132;
            int cc = i % 132;
            int yy = y0 + r - 1;
            int xx = cc - 1;
            float v = 0.f;
            if (yy >= 0 && yy < Hh && xx >= 0 && xx < Ww)
                v = xb[c * HW + yy * Ww + xx];
            xr[r][cc] = v;
        }
        __syncthreads();

#pragma unroll
        for (int ky = 0; ky < 3; ky++) {
#pragma unroll
            for (int kx = 0; kx < 3; kx++) {
                float xv0 = xr[ky][tx + kx];
                float xv1 = xr[ky + 1][tx + kx];
#pragma unroll
                for (int ch = 0; ch < 18; ch++) {
                    float w = ws[ch * 9 + ky * 3 + kx];
                    acc0[ch] = fmaf(w, xv0, acc0[ch]);
                    acc1[ch] = fmaf(w, xv1, acc1[ch]);
                }
            }
        }
    }

#pragma unroll
    for (int ch = 0; ch < 18; ch++) {
        float bias = bp[ch];
        g_offset[((b * 18 + ch) * Hh + y0) * Ww + tx]       = acc0[ch] + bias;
        g_offset[((b * 18 + ch) * Hh + y0 + 1) * Ww + tx]   = acc1[ch] + bias;
    }
}

// ======================================================================
// Kernel 3: fused bilinear gather + GEMM
//   out[b,o,y,x] = sum_n sum_c wt[n][c][o] * xs(b,c,y,x,n)
// Tile: 256 outputs x 32 pixels, BK = 32 channels, n-major K loop.
// 256 threads; each thread: 8 o x 4 pix accumulators.
// ======================================================================
__global__ void __launch_bounds__(256, 2) ldconv_main_k(
    const float* __restrict__ x,
    float* __restrict__ out)
{
    const int b  = blockIdx.y;
    const int pb = blockIdx.x;           // 0..2047
    const int y  = pb >> 2;
    const int x0 = (pb & 3) * BPIX;

    const float* xb = x + (size_t)b * Cc * HW;

    __shared__ float  wsm[32][OUTC];     // 32 KB : A tile [kk][o]
    __shared__ float  xssm[32][BPIX];    //  4 KB : B tile [kk][pix]
    __shared__ float4 gsm4[NP][BPIX];    // 4.5 KB: bilinear weights
    __shared__ int4   ism4[NP][BPIX];    // 4.5 KB: gather indices

    const int t = threadIdx.x;

    // ---- prologue: bilinear metadata for 32 pixels x 9 offsets ----
    for (int task = t; task < NP * BPIX; task += 256) {
        int n  = task / BPIX;
        int px = task % BPIX;
        int xx = x0 + px;
        float offr = g_offset[((b * 18 + n) * Hh + y) * Ww + xx];
        float offc = g_offset[((b * 18 + NP + n) * Hh + y) * Ww + xx];
        float pr = (float)y  + (float)(n / 3) + offr;   // row coord
        float pc = (float)xx + (float)(n % 3) + offc;   // col coord

        float ltr = floorf(pr), ltc = floorf(pc);
        float rbr = ltr + 1.f,  rbc = ltc + 1.f;
        ltr = fminf(fmaxf(ltr, 0.f), 127.f);
        rbr = fminf(fmaxf(rbr, 0.f), 127.f);
        ltc = fminf(fmaxf(ltc, 0.f), 127.f);
        rbc = fminf(fmaxf(rbc, 0.f), 127.f);
        pr  = fminf(fmaxf(pr, 0.f), 127.f);
        pc  = fminf(fmaxf(pc, 0.f), 127.f);

        float dr_lt = 1.f + (ltr - pr);
        float dr_rb = 1.f - (rbr - pr);
        float dc_lt = 1.f + (ltc - pc);
        float dc_rb = 1.f - (rbc - pc);

        float4 g;
        g.x = dr_lt * dc_lt;   // lt
        g.y = dr_rb * dc_rb;   // rb
        g.z = dr_lt * dc_rb;   // lb = (lt_row, rb_col)
        g.w = dr_rb * dc_lt;   // rt = (rb_row, lt_col)
        gsm4[n][px] = g;

        int iltr = (int)ltr, iltc = (int)ltc;
        int irbr = (int)rbr, irbc = (int)rbc;
        int4 iv;
        iv.x = iltr * Ww + iltc;
        iv.y = irbr * Ww + irbc;
        iv.z = iltr * Ww + irbc;
        iv.w = irbr * Ww + iltc;
        ism4[n][px] = iv;
    }
    __syncthreads();

    float acc[8][4];
#pragma unroll
    for (int i = 0; i < 8; i++)
#pragma unroll
        for (int j = 0; j < 4; j++) acc[i][j] = 0.f;

    const int tm = t & 31;   // o-group  (o = tm*4..+3 and 128+tm*4..+3)
    const int tn = t >> 5;   // pix-group (pix = tn*4..+3)

    const int px  = t & 31;  // pixel this thread gathers for
    const int kk0 = t >> 5;  // base kk for gather (0..7)

    for (int nn = 0; nn < NP; nn++) {
        float4 gv = gsm4[nn][px];
        int4   iv = ism4[nn][px];
        for (int cc = 0; cc < 4; cc++) {
            const int c0 = cc * 32;

            // ---- load A tile: wt[(nn*128 + c0 + kk)*256 + o] ----
            const float4* wsrc = (const float4*)(g_wt + (nn * Cc + c0) * OUTC);
#pragma unroll
            for (int i = 0; i < 8; i++) {
                ((float4*)wsm)[t + i * 256] = wsrc[t + i * 256];
            }

            // ---- build B tile: gathered bilinear samples ----
            const float* xcb = xb + c0 * HW;
#pragma unroll
            for (int i = 0; i < 4; i++) {
                int kk = kk0 + i * 8;
                const float* xc = xcb + kk * HW;
                float v = gv.x * __ldg(xc + iv.x)
                        + gv.y * __ldg(xc + iv.y)
                        + gv.z * __ldg(xc + iv.z)
                        + gv.w * __ldg(xc + iv.w);
                xssm[kk][px] = v;
            }
            __syncthreads();

            // ---- FFMA micro-kernel ----
#pragma unroll
            for (int kk = 0; kk < 32; kk++) {
                float4 a0 = *(const float4*)&wsm[kk][tm * 4];
                float4 a1 = *(const float4*)&wsm[kk][128 + tm * 4];
                float4 b0 = *(const float4*)&xssm[kk][tn * 4];
                float a[8] = {a0.x, a0.y, a0.z, a0.w, a1.x, a1.y, a1.z, a1.w};
                float bb[4] = {b0.x, b0.y, b0.z, b0.w};
#pragma unroll
                for (int i = 0; i < 8; i++)
#pragma unroll
                    for (int j = 0; j < 4; j++)
                        acc[i][j] = fmaf(a[i], bb[j], acc[i][j]);
            }
            __syncthreads();
        }
    }

    // ---- epilogue ----
#pragma unroll
    for (int i = 0; i < 8; i++) {
        int o = (i < 4) ? (tm * 4 + i) : (128 + tm * 4 + (i - 4));
        float4 v;
        v.x = acc[i][0]; v.y = acc[i][1]; v.z = acc[i][2]; v.w = acc[i][3];
        *(float4*)(out + ((size_t)(b * OUTC + o) * HW) + y * Ww + x0 + tn * 4) = v;
    }
}

// ======================================================================
// launch
// ======================================================================
extern "C" void kernel_launch(void* const* d_in, const int* in_sizes, int n_in,
                              void* d_out, int out_size)
{
    // robust input identification by element count
    const float* x  = nullptr;   // 4*128*128*128 = 8388608
    const float* wp = nullptr;   // 18*128*3*3    = 20736
    const float* bp = nullptr;   // 18
    const float* wc = nullptr;   // 256*128*9*1   = 294912
    for (int i = 0; i < n_in; i++) {
        switch (in_sizes[i]) {
            case 8388608: x  = (const float*)d_in[i]; break;
            case 20736:   wp = (const float*)d_in[i]; break;
            case 18:      bp = (const float*)d_in[i]; break;
            case 294912:  wc = (const float*)d_in[i]; break;
            default: break;
        }
    }
    // fallback to positional order if sizes were unexpected
    if (!x)  x  = (const float*)d_in[0];
    if (!wp) wp = (const float*)d_in[1];
    if (!bp) bp = (const float*)d_in[2];
    if (!wc) wc = (const float*)d_in[3];

    float* out = (float*)d_out;

    wtrans_k<<<(NP * Cc * OUTC + 255) / 256, 256>>>(wc);
    offset_conv_k<<<dim3(Hh / 2, Bb), 128>>>(x, wp, bp);
    ldconv_main_k<<<dim3((HW / BPIX), Bb), 256>>>(x, out);
}

// round 3
// speedup vs baseline: 1.0074x; 1.0074x over previous
#include <cuda_runtime.h>
#include <cstdint>

#define Hh   128
#define Ww   128
#define HW   16384
#define Cc   128
#define NP   9
#define OUTC 256
#define Bb   4
#define BPIX 32

// -------- device scratch (no allocations allowed) --------
__device__ float g_offset[Bb * 2 * NP * HW];   // (b, 18, H, W)
__device__ float g_wt[NP * Cc * OUTC];         // [n][c][o]

// ======================================================================
// Kernel 1: transpose w_conv (outc, C, N, 1) -> wt[n][c][o]
// ======================================================================
__global__ void wtrans_k(const float* __restrict__ wc) {
    int i = blockIdx.x * 256 + threadIdx.x;      // 0 .. 9*128*256-1
    if (i < NP * Cc * OUTC) {
        int o = i % OUTC;
        int r = i / OUTC;
        int c = r % Cc;
        int n = r / Cc;
        g_wt[i] = wc[(o * Cc + c) * NP + n];
    }
}

// ======================================================================
// Kernel 2: offset conv: x (b,C,H,W) * w_p (18,C,3,3) pad 1 stride 1
// Each block: one batch, two rows. 128 threads (one x-column each,
// two rows per thread).
// ======================================================================
__global__ void __launch_bounds__(128) offset_conv_k(
    const float* __restrict__ x,
    const float* __restrict__ wp,
    const float* __restrict__ bp)
{
    const int y0 = blockIdx.x * 2;
    const int b  = blockIdx.y;
    const int tx = threadIdx.x;

    __shared__ float xr[4][132];
    __shared__ float ws[168];

    float acc0[18];
    float acc1[18];
#pragma unroll
    for (int ch = 0; ch < 18; ch++) { acc0[ch] = 0.f; acc1[ch] = 0.f; }

    const float* xb = x + (size_t)b * Cc * HW;

    for (int c = 0; c < Cc; c++) {
        __syncthreads();
        // weights for this input channel: 18*9 = 162 floats
        for (int i = tx; i < 162; i += 128) {
            ws[i] = wp[(i / 9) * (Cc * 9) + c * 9 + (i % 9)];
        }
        // x rows y0-1 .. y0+2, cols -1 .. 128 (zero pad)
        for (int i = tx; i < 4 * 132; i += 128) {
            int r  = i / 132;
            int cc = i % 132;
            int yy = y0 + r - 1;
            int xx = cc - 1;
            float v = 0.f;
            if (yy >= 0 && yy < Hh && xx >= 0 && xx < Ww)
                v = xb[c * HW + yy * Ww + xx];
            xr[r][cc] = v;
        }
        __syncthreads();

#pragma unroll
        for (int ky = 0; ky < 3; ky++) {
#pragma unroll
            for (int kx = 0; kx < 3; kx++) {
                float xv0 = xr[ky][tx + kx];
                float xv1 = xr[ky + 1][tx + kx];
#pragma unroll
                for (int ch = 0; ch < 18; ch++) {
                    float w = ws[ch * 9 + ky * 3 + kx];
                    acc0[ch] = fmaf(w, xv0, acc0[ch]);
                    acc1[ch] = fmaf(w, xv1, acc1[ch]);
                }
            }
        }
    }

#pragma unroll
    for (int ch = 0; ch < 18; ch++) {
        float bias = bp[ch];
        g_offset[((b * 18 + ch) * Hh + y0) * Ww + tx]       = acc0[ch] + bias;
        g_offset[((b * 18 + ch) * Hh + y0 + 1) * Ww + tx]   = acc1[ch] + bias;
    }
}

// ======================================================================
// Kernel 3: fused bilinear gather + GEMM
//   out[b,o,y,x] = sum_n sum_c wt[n][c][o] * xs(b,c,y,x,n)
// Tile: 256 outputs x 32 pixels, BK = 32 channels, n-major K loop.
// 256 threads; each thread: 8 o x 4 pix accumulators.
// ======================================================================
__global__ void __launch_bounds__(256, 2) ldconv_main_k(
    const float* __restrict__ x,
    float* __restrict__ out)
{
    const int b  = blockIdx.y;
    const int pb = blockIdx.x;           // 0..2047
    const int y  = pb >> 2;
    const int x0 = (pb & 3) * BPIX;

    const float* xb = x + (size_t)b * Cc * HW;

    __shared__ float  wsm[32][OUTC];     // 32 KB : A tile [kk][o]
    __shared__ float  xssm[32][BPIX];    //  4 KB : B tile [kk][pix]
    __shared__ float4 gsm4[NP][BPIX];    // 4.5 KB: bilinear weights
    __shared__ int4   ism4[NP][BPIX];    // 4.5 KB: gather indices

    const int t = threadIdx.x;

    // ---- prologue: bilinear metadata for 32 pixels x 9 offsets ----
    for (int task = t; task < NP * BPIX; task += 256) {
        int n  = task / BPIX;
        int px = task % BPIX;
        int xx = x0 + px;
        float offr = g_offset[((b * 18 + n) * Hh + y) * Ww + xx];
        float offc = g_offset[((b * 18 + NP + n) * Hh + y) * Ww + xx];
        float pr = (float)y  + (float)(n / 3) + offr;   // row coord
        float pc = (float)xx + (float)(n % 3) + offc;   // col coord

        float ltr = floorf(pr), ltc = floorf(pc);
        float rbr = ltr + 1.f,  rbc = ltc + 1.f;
        ltr = fminf(fmaxf(ltr, 0.f), 127.f);
        rbr = fminf(fmaxf(rbr, 0.f), 127.f);
        ltc = fminf(fmaxf(ltc, 0.f), 127.f);
        rbc = fminf(fmaxf(rbc, 0.f), 127.f);
        pr  = fminf(fmaxf(pr, 0.f), 127.f);
        pc  = fminf(fmaxf(pc, 0.f), 127.f);

        float dr_lt = 1.f + (ltr - pr);
        float dr_rb = 1.f - (rbr - pr);
        float dc_lt = 1.f + (ltc - pc);
        float dc_rb = 1.f - (rbc - pc);

        float4 g;
        g.x = dr_lt * dc_lt;   // lt
        g.y = dr_rb * dc_rb;   // rb
        g.z = dr_lt * dc_rb;   // lb = (lt_row, rb_col)
        g.w = dr_rb * dc_lt;   // rt = (rb_row, lt_col)
        gsm4[n][px] = g;

        int iltr = (int)ltr, iltc = (int)ltc;
        int irbr = (int)rbr, irbc = (int)rbc;
        int4 iv;
        iv.x = iltr * Ww + iltc;
        iv.y = irbr * Ww + irbc;
        iv.z = iltr * Ww + irbc;
        iv.w = irbr * Ww + iltc;
        ism4[n][px] = iv;
    }
    __syncthreads();

    float acc[8][4];
#pragma unroll
    for (int i = 0; i < 8; i++)
#pragma unroll
        for (int j = 0; j < 4; j++) acc[i][j] = 0.f;

    const int tm = t & 31;   // o-group  (o = tm*4..+3 and 128+tm*4..+3)
    const int tn = t >> 5;   // pix-group (pix = tn*4..+3)

    const int px  = t & 31;  // pixel this thread gathers for
    const int kk0 = t >> 5;  // base kk for gather (0..7)

    for (int nn = 0; nn < NP; nn++) {
        float4 gv = gsm4[nn][px];
        int4   iv = ism4[nn][px];
        for (int cc = 0; cc < 4; cc++) {
            const int c0 = cc * 32;

            // ---- load A tile: wt[(nn*128 + c0 + kk)*256 + o] ----
            const float4* wsrc = (const float4*)(g_wt + (nn * Cc + c0) * OUTC);
#pragma unroll
            for (int i = 0; i < 8; i++) {
                ((float4*)wsm)[t + i * 256] = wsrc[t + i * 256];
            }

            // ---- build B tile: gathered bilinear samples ----
            const float* xcb = xb + c0 * HW;
#pragma unroll
            for (int i = 0; i < 4; i++) {
                int kk = kk0 + i * 8;
                const float* xc = xcb + kk * HW;
                float v = gv.x * __ldg(xc + iv.x)
                        + gv.y * __ldg(xc + iv.y)
                        + gv.z * __ldg(xc + iv.z)
                        + gv.w * __ldg(xc + iv.w);
                xssm[kk][px] = v;
            }
            __syncthreads();

            // ---- FFMA micro-kernel ----
#pragma unroll
            for (int kk = 0; kk < 32; kk++) {
                float4 a0 = *(const float4*)&wsm[kk][tm * 4];
                float4 a1 = *(const float4*)&wsm[kk][128 + tm * 4];
                float4 b0 = *(const float4*)&xssm[kk][tn * 4];
                float a[8] = {a0.x, a0.y, a0.z, a0.w, a1.x, a1.y, a1.z, a1.w};
                float bb[4] = {b0.x, b0.y, b0.z, b0.w};
#pragma unroll
                for (int i = 0; i < 8; i++)
#pragma unroll
                    for (int j = 0; j < 4; j++)
                        acc[i][j] = fmaf(a[i], bb[j], acc[i][j]);
            }
            __syncthreads();
        }
    }

    // ---- epilogue ----
#pragma unroll
    for (int i = 0; i < 8; i++) {
        int o = (i < 4) ? (tm * 4 + i) : (128 + tm * 4 + (i - 4));
        float4 v;
        v.x = acc[i][0]; v.y = acc[i][1]; v.z = acc[i][2]; v.w = acc[i][3];
        *(float4*)(out + ((size_t)(b * OUTC + o) * HW) + y * Ww + x0 + tn * 4) = v;
    }
}

// ======================================================================
// launch
// ======================================================================
extern "C" void kernel_launch(void* const* d_in, const int* in_sizes, int n_in,
                              void* d_out, int out_size)
{
    // robust input identification by element count
    const float* x  = nullptr;   // 4*128*128*128 = 8388608
    const float* wp = nullptr;   // 18*128*3*3    = 20736
    const float* bp = nullptr;   // 18
    const float* wc = nullptr;   // 256*128*9*1   = 294912
    for (int i = 0; i < n_in; i++) {
        switch (in_sizes[i]) {
            case 8388608: x  = (const float*)d_in[i]; break;
            case 20736:   wp = (const float*)d_in[i]; break;
            case 18:      bp = (const float*)d_in[i]; break;
            case 294912:  wc = (const float*)d_in[i]; break;
            default: break;
        }
    }
    // fallback to positional order if sizes were unexpected
    if (!x)  x  = (const float*)d_in[0];
    if (!wp) wp = (const float*)d_in[1];
    if (!bp) bp = (const float*)d_in[2];
    if (!wc) wc = (const float*)d_in[3];

    float* out = (float*)d_out;

    wtrans_k<<<(NP * Cc * OUTC + 255) / 256, 256>>>(wc);
    offset_conv_k<<<dim3(Hh / 2, Bb), 128>>>(x, wp, bp);
    ldconv_main_k<<<dim3((HW / BPIX), Bb), 256>>>(x, out);
}

// round 4
// speedup vs baseline: 1.1890x; 1.1803x over previous
#include <cuda_runtime.h>
#include <cstdint>

#define Hh   128
#define Ww   128
#define HW   16384
#define Cc   128
#define NP   9
#define OUTC 256
#define Bb   4
#define BPIX 64

typedef unsigned long long ull;

// -------- device scratch (no allocations allowed) --------
__device__ float g_offset[Bb * 2 * NP * HW];   // (b, 18, H, W)
__device__ float g_wt[NP * Cc * OUTC];         // [n][c][o]

// ---------------- packed f32x2 helpers ----------------
__device__ __forceinline__ void ffma2(ull& d, ull a, ull b) {
    asm("fma.rn.f32x2 %0, %1, %2, %0;" : "+l"(d) : "l"(a), "l"(b));
}
__device__ __forceinline__ ull pack2(float lo, float hi) {
    ull r; asm("mov.b64 %0, {%1, %2};" : "=l"(r) : "f"(lo), "f"(hi)); return r;
}
__device__ __forceinline__ float2 unpack2(ull v) {
    float2 f; asm("mov.b64 {%0, %1}, %2;" : "=f"(f.x), "=f"(f.y) : "l"(v)); return f;
}

// ======================================================================
// Kernel 1: transpose w_conv (outc, C, N, 1) -> wt[n][c][o]
// ======================================================================
__global__ void wtrans_k(const float* __restrict__ wc) {
    int i = blockIdx.x * 256 + threadIdx.x;
    if (i < NP * Cc * OUTC) {
        int o = i % OUTC;
        int r = i / OUTC;
        int c = r % Cc;
        int n = r / Cc;
        g_wt[i] = wc[(o * Cc + c) * NP + n];
    }
}

// ======================================================================
// Kernel 2: offset conv (FFMA2 version): x (b,C,H,W) * w_p (18,C,3,3)
// pad 1, stride 1. Block = (batch, 2 rows). 128 threads (one column each).
// Accumulators are channel-PAIRS packed in f32x2.
// ======================================================================
__global__ void __launch_bounds__(128) offset_conv_k(
    const float* __restrict__ x,
    const float* __restrict__ wp,
    const float* __restrict__ bp)
{
    const int y0 = blockIdx.x * 2;
    const int b  = blockIdx.y;
    const int tx = threadIdx.x;

    __shared__ float xr[4][132];
    __shared__ float ws2[9][18];     // [tap k][out-channel], ch pairs contiguous

    ull acc0[9], acc1[9];
#pragma unroll
    for (int p = 0; p < 9; p++) { acc0[p] = 0ULL; acc1[p] = 0ULL; }

    const float* xb = x + (size_t)b * Cc * HW;

    for (int c = 0; c < Cc; c++) {
        __syncthreads();
        // weights: ws2[k][ch] = wp[ch, c, k]
        for (int i = tx; i < 162; i += 128) {
            int k  = i / 18;
            int ch = i % 18;
            ws2[k][ch] = wp[ch * (Cc * 9) + c * 9 + k];
        }
        // x rows y0-1 .. y0+2, cols -1 .. 128 (zero pad)
        for (int i = tx; i < 4 * 132; i += 128) {
            int r  = i / 132;
            int cc = i % 132;
            int yy = y0 + r - 1;
            int xx = cc - 1;
            float v = 0.f;
            if (yy >= 0 && yy < Hh && xx >= 0 && xx < Ww)
                v = xb[c * HW + yy * Ww + xx];
            xr[r][cc] = v;
        }
        __syncthreads();

#pragma unroll
        for (int k = 0; k < 9; k++) {
            const int ky = k / 3, kx = k % 3;
            float xv0 = xr[ky][tx + kx];
            float xv1 = xr[ky + 1][tx + kx];
            ull x0d = pack2(xv0, xv0);
            ull x1d = pack2(xv1, xv1);
            const ull* wrow = (const ull*)&ws2[k][0];
#pragma unroll
            for (int p = 0; p < 9; p++) {
                ull wpair = wrow[p];
                ffma2(acc0[p], wpair, x0d);
                ffma2(acc1[p], wpair, x1d);
            }
        }
    }

#pragma unroll
    for (int p = 0; p < 9; p++) {
        float2 a0 = unpack2(acc0[p]);
        float2 a1 = unpack2(acc1[p]);
        int ch0 = 2 * p, ch1 = 2 * p + 1;
        float b0 = bp[ch0], b1 = bp[ch1];
        g_offset[((b * 18 + ch0) * Hh + y0) * Ww + tx]     = a0.x + b0;
        g_offset[((b * 18 + ch1) * Hh + y0) * Ww + tx]     = a0.y + b1;
        g_offset[((b * 18 + ch0) * Hh + y0 + 1) * Ww + tx] = a1.x + b0;
        g_offset[((b * 18 + ch1) * Hh + y0 + 1) * Ww + tx] = a1.y + b1;
    }
}

// ======================================================================
// Kernel 3: fused bilinear gather + GEMM (FFMA2 micro-kernel)
//   out[b,o,y,x] = sum_n sum_c wt[n][c][o] * xs(b,c,y,x,n)
// Block tile: 256 outputs x 64 pixels, BK = 32, n-major K loop (36 tiles).
// 256 threads; each thread: 8 o x 8 px accumulators as 4 o-pairs x 8 px f32x2.
// ======================================================================
__global__ void __launch_bounds__(256, 2) ldconv_main_k(
    const float* __restrict__ x,
    float* __restrict__ out)
{
    const int b  = blockIdx.y;
    const int pb = blockIdx.x;           // 0..255
    const int y  = pb >> 1;
    const int x0 = (pb & 1) * BPIX;

    const float* xb = x + (size_t)b * Cc * HW;

    __shared__ float  wsm[32][OUTC];     // 32 KB : A tile [kk][o]
    __shared__ float  xssm[32][BPIX];    //  8 KB : B tile [kk][pix]
    __shared__ float4 gsm4[NP][BPIX];    //  9 KB : bilinear weights
    __shared__ int4   ism4[NP][BPIX];    //  9 KB : gather indices

    const int t = threadIdx.x;

    // ---- prologue: bilinear metadata for 64 pixels x 9 offsets ----
    for (int task = t; task < NP * BPIX; task += 256) {
        int n  = task / BPIX;
        int px = task % BPIX;
        int xx = x0 + px;
        float offr = g_offset[((b * 18 + n) * Hh + y) * Ww + xx];
        float offc = g_offset[((b * 18 + NP + n) * Hh + y) * Ww + xx];
        float pr = (float)y  + (float)(n / 3) + offr;
        float pc = (float)xx + (float)(n % 3) + offc;

        float ltr = floorf(pr), ltc = floorf(pc);
        float rbr = ltr + 1.f,  rbc = ltc + 1.f;
        ltr = fminf(fmaxf(ltr, 0.f), 127.f);
        rbr = fminf(fmaxf(rbr, 0.f), 127.f);
        ltc = fminf(fmaxf(ltc, 0.f), 127.f);
        rbc = fminf(fmaxf(rbc, 0.f), 127.f);
        pr  = fminf(fmaxf(pr, 0.f), 127.f);
        pc  = fminf(fmaxf(pc, 0.f), 127.f);

        float dr_lt = 1.f + (ltr - pr);
        float dr_rb = 1.f - (rbr - pr);
        float dc_lt = 1.f + (ltc - pc);
        float dc_rb = 1.f - (rbc - pc);

        float4 g;
        g.x = dr_lt * dc_lt;   // lt
        g.y = dr_rb * dc_rb;   // rb
        g.z = dr_lt * dc_rb;   // lb
        g.w = dr_rb * dc_lt;   // rt
        gsm4[n][px] = g;

        int iltr = (int)ltr, iltc = (int)ltc;
        int irbr = (int)rbr, irbc = (int)rbc;
        int4 iv;
        iv.x = iltr * Ww + iltc;
        iv.y = irbr * Ww + irbc;
        iv.z = iltr * Ww + irbc;
        iv.w = irbr * Ww + iltc;
        ism4[n][px] = iv;
    }
    __syncthreads();

    ull acc2[4][8];
#pragma unroll
    for (int i = 0; i < 4; i++)
#pragma unroll
        for (int j = 0; j < 8; j++) acc2[i][j] = 0ULL;

    const int tm = t & 31;   // o-group: o = tm*4..+3 and 128+tm*4..+3
    const int tn = t >> 5;   // pix-group: px = tn*8..+7

    const int px  = t & 63;  // pixel this thread gathers for
    const int kk0 = t >> 6;  // 0..3

    for (int nn = 0; nn < NP; nn++) {
        float4 gv = gsm4[nn][px];
        int4   iv = ism4[nn][px];
        for (int cc = 0; cc < 4; cc++) {
            const int c0 = cc * 32;

            // ---- load A tile: wt[(nn*128 + c0 + kk)*256 + o] ----
            const float4* wsrc = (const float4*)(g_wt + (nn * Cc + c0) * OUTC);
#pragma unroll
            for (int i = 0; i < 8; i++) {
                ((float4*)wsm)[t + i * 256] = wsrc[t + i * 256];
            }

            // ---- build B tile: gathered bilinear samples ----
            const float* xcb = xb + c0 * HW;
#pragma unroll
            for (int i = 0; i < 8; i++) {
                int kk = kk0 * 8 + i;
                const float* xc = xcb + kk * HW;
                float v = gv.x * __ldg(xc + iv.x)
                        + gv.y * __ldg(xc + iv.y)
                        + gv.z * __ldg(xc + iv.z)
                        + gv.w * __ldg(xc + iv.w);
                xssm[kk][px] = v;
            }
            __syncthreads();

            // ---- FFMA2 micro-kernel: 4 o-pairs x 8 px per kk ----
#pragma unroll 8
            for (int kk = 0; kk < 32; kk++) {
                ulonglong2 A0 = *(const ulonglong2*)&wsm[kk][tm * 4];
                ulonglong2 A1 = *(const ulonglong2*)&wsm[kk][128 + tm * 4];
                float4 b0 = *(const float4*)&xssm[kk][tn * 8];
                float4 b1 = *(const float4*)&xssm[kk][tn * 8 + 4];
                ull ad[4] = {A0.x, A0.y, A1.x, A1.y};
                ull bd[8];
                bd[0] = pack2(b0.x, b0.x);
                bd[1] = pack2(b0.y, b0.y);
                bd[2] = pack2(b0.z, b0.z);
                bd[3] = pack2(b0.w, b0.w);
                bd[4] = pack2(b1.x, b1.x);
                bd[5] = pack2(b1.y, b1.y);
                bd[6] = pack2(b1.z, b1.z);
                bd[7] = pack2(b1.w, b1.w);
#pragma unroll
                for (int i = 0; i < 4; i++)
#pragma unroll
                    for (int j = 0; j < 8; j++)
                        ffma2(acc2[i][j], ad[i], bd[j]);
            }
            __syncthreads();
        }
    }

    // ---- epilogue: acc2[i][j] holds outputs (o0, o1) of pair i at px j ----
#pragma unroll
    for (int i = 0; i < 4; i++) {
        float lo[8], hi[8];
#pragma unroll
        for (int j = 0; j < 8; j++) {
            float2 f = unpack2(acc2[i][j]);
            lo[j] = f.x; hi[j] = f.y;
        }
        int o0 = (i < 2) ? (tm * 4 + 2 * i) : (128 + tm * 4 + 2 * (i - 2));
        float* p0 = out + (size_t)(b * OUTC + o0) * HW + y * Ww + x0 + tn * 8;
        float* p1 = p0 + HW;
        *(float4*)(p0)     = make_float4(lo[0], lo[1], lo[2], lo[3]);
        *(float4*)(p0 + 4) = make_float4(lo[4], lo[5], lo[6], lo[7]);
        *(float4*)(p1)     = make_float4(hi[0], hi[1], hi[2], hi[3]);
        *(float4*)(p1 + 4) = make_float4(hi[4], hi[5], hi[6], hi[7]);
    }
}

// ======================================================================
// launch
// ======================================================================
extern "C" void kernel_launch(void* const* d_in, const int* in_sizes, int n_in,
                              void* d_out, int out_size)
{
    const float* x  = nullptr;   // 4*128*128*128 = 8388608
    const float* wp = nullptr;   // 18*128*3*3    = 20736
    const float* bp = nullptr;   // 18
    const float* wc = nullptr;   // 256*128*9*1   = 294912
    for (int i = 0; i < n_in; i++) {
        switch (in_sizes[i]) {
            case 8388608: x  = (const float*)d_in[i]; break;
            case 20736:   wp = (const float*)d_in[i]; break;
            case 18:      bp = (const float*)d_in[i]; break;
            case 294912:  wc = (const float*)d_in[i]; break;
            default: break;
        }
    }
    if (!x)  x  = (const float*)d_in[0];
    if (!wp) wp = (const float*)d_in[1];
    if (!bp) bp = (const float*)d_in[2];
    if (!wc) wc = (const float*)d_in[3];

    float* out = (float*)d_out;

    wtrans_k<<<(NP * Cc * OUTC + 255) / 256, 256>>>(wc);
    offset_conv_k<<<dim3(Hh / 2, Bb), 128>>>(x, wp, bp);
    ldconv_main_k<<<dim3(HW / BPIX, Bb), 256>>>(x, out);
}

// round 6
// speedup vs baseline: 1.5833x; 1.3316x over previous
#include <cuda_runtime.h>
#include <cuda_bf16.h>
#include <cstdint>

#define Hh   128
#define Ww   128
#define HW   16384
#define Cc   128
#define NP   9
#define OUTC 256
#define Bb   4
#define BK   64
#define NT   18          // K tiles (K = 1152)
#define NPX  128         // pixels per CTA (one image row)
#define NTHR 512

typedef unsigned long long ull;
typedef unsigned int u32;

// -------- device scratch --------
__device__ float g_offset[Bb * 2 * NP * HW];            // (b, 18, H, W)
__device__ __nv_bfloat16 g_wa_hi[NT * OUTC * BK];       // [tile][o][j]
__device__ __nv_bfloat16 g_wa_lo[NT * OUTC * BK];

// ---------------- helpers ----------------
__device__ __forceinline__ u32 smem_u32(const void* p) {
    u32 a;
    asm("{ .reg .u64 t; cvta.to.shared.u64 t, %1; cvt.u32.u64 %0, t; }" : "=r"(a) : "l"(p));
    return a;
}
__device__ __forceinline__ void ldsm_x4(u32& r0, u32& r1, u32& r2, u32& r3, u32 addr) {
    asm volatile("ldmatrix.sync.aligned.m8n8.x4.shared.b16 {%0,%1,%2,%3}, [%4];"
                 : "=r"(r0), "=r"(r1), "=r"(r2), "=r"(r3) : "r"(addr));
}
__device__ __forceinline__ void mma_bf16(float* d, const u32* a, const u32* b) {
    asm("mma.sync.aligned.m16n8k16.row.col.f32.bf16.bf16.f32 "
        "{%0,%1,%2,%3},{%4,%5,%6,%7},{%8,%9},{%0,%1,%2,%3};"
        : "+f"(d[0]), "+f"(d[1]), "+f"(d[2]), "+f"(d[3])
        : "r"(a[0]), "r"(a[1]), "r"(a[2]), "r"(a[3]), "r"(b[0]), "r"(b[1]));
}
__device__ __forceinline__ u32 swz(u32 off) { return off ^ ((off >> 3) & 0x70); }

// packed f32x2 helpers (offset conv)
__device__ __forceinline__ void ffma2(ull& d, ull a, ull b) {
    asm("fma.rn.f32x2 %0, %1, %2, %0;" : "+l"(d) : "l"(a), "l"(b));
}
__device__ __forceinline__ ull pack2(float lo, float hi) {
    ull r; asm("mov.b64 %0, {%1, %2};" : "=l"(r) : "f"(lo), "f"(hi)); return r;
}
__device__ __forceinline__ float2 unpack2(ull v) {
    float2 f; asm("mov.b64 {%0, %1}, %2;" : "=f"(f.x), "=f"(f.y) : "l"(v)); return f;
}

// ======================================================================
// Kernel 1: w_conv (outc, C, N, 1) -> tiled bf16 hi/lo A: [tile][o][j]
// k = tile*64 + j, n = k/128, c = k%128
// ======================================================================
__global__ void wtrans_k(const float* __restrict__ wc) {
    int i = blockIdx.x * 256 + threadIdx.x;
    if (i < NT * OUTC * BK) {
        int j = i & 63;
        int o = (i >> 6) & 255;
        int tt = i >> 14;
        int k = tt * 64 + j;
        int n = k >> 7;
        int c = k & 127;
        float w = wc[(o * Cc + c) * NP + n];
        __nv_bfloat16 h = __float2bfloat16_rn(w);
        float hf = __bfloat162float(h);
        __nv_bfloat16 l = __float2bfloat16_rn(w - hf);
        g_wa_hi[i] = h;
        g_wa_lo[i] = l;
    }
}

// ======================================================================
// Kernel 2: offset conv (proven, unchanged)
// ======================================================================
__global__ void __launch_bounds__(128) offset_conv_k(
    const float* __restrict__ x,
    const float* __restrict__ wp,
    const float* __restrict__ bp)
{
    const int y0 = blockIdx.x * 2;
    const int b  = blockIdx.y;
    const int tx = threadIdx.x;

    __shared__ float xr[4][132];
    __shared__ float ws2[9][18];

    ull acc0[9], acc1[9];
#pragma unroll
    for (int p = 0; p < 9; p++) { acc0[p] = 0ULL; acc1[p] = 0ULL; }

    const float* xb = x + (size_t)b * Cc * HW;

    for (int c = 0; c < Cc; c++) {
        __syncthreads();
        for (int i = tx; i < 162; i += 128) {
            int k  = i / 18;
            int ch = i % 18;
            ws2[k][ch] = wp[ch * (Cc * 9) + c * 9 + k];
        }
        for (int i = tx; i < 4 * 132; i += 128) {
            int r  = i / 132;
            int cc = i % 132;
            int yy = y0 + r - 1;
            int xx = cc - 1;
            float v = 0.f;
            if (yy >= 0 && yy < Hh && xx >= 0 && xx < Ww)
                v = xb[c * HW + yy * Ww + xx];
            xr[r][cc] = v;
        }
        __syncthreads();

#pragma unroll
        for (int k = 0; k < 9; k++) {
            const int ky = k / 3, kx = k % 3;
            float xv0 = xr[ky][tx + kx];
            float xv1 = xr[ky + 1][tx + kx];
            ull x0d = pack2(xv0, xv0);
            ull x1d = pack2(xv1, xv1);
            const ull* wrow = (const ull*)&ws2[k][0];
#pragma unroll
            for (int p = 0; p < 9; p++) {
                ull wpair = wrow[p];
                ffma2(acc0[p], wpair, x0d);
                ffma2(acc1[p], wpair, x1d);
            }
        }
    }

#pragma unroll
    for (int p = 0; p < 9; p++) {
        float2 a0 = unpack2(acc0[p]);
        float2 a1 = unpack2(acc1[p]);
        int ch0 = 2 * p, ch1 = 2 * p + 1;
        float b0 = bp[ch0], b1 = bp[ch1];
        g_offset[((b * 18 + ch0) * Hh + y0) * Ww + tx]     = a0.x + b0;
        g_offset[((b * 18 + ch1) * Hh + y0) * Ww + tx]     = a0.y + b1;
        g_offset[((b * 18 + ch0) * Hh + y0 + 1) * Ww + tx] = a1.x + b0;
        g_offset[((b * 18 + ch1) * Hh + y0 + 1) * Ww + tx] = a1.y + b1;
    }
}

// ======================================================================
// Kernel 3: fused gather + warp-MMA bf16 3-split GEMM
// CTA = (batch b, row y): out[b, 0..255, y, 0..127]
// 512 threads = 16 warps; warp tile M=64 x N=32.
// ======================================================================
// SMEM layout (bytes from dynamic base):
#define S_METAW 0                          // float4[1152]  -> 18432
#define S_METAI 18432                      // ushort4[1152] ->  9216
#define S_BUF0  27648
// per buffer: Ah 32768 | Al 32768 | Bh 16384 | Bl 16384  = 98304
#define S_BUFSZ 98304
#define S_AH 0
#define S_AL 32768
#define S_BH 65536
#define S_BL 81920
#define S_TOTAL (S_BUF0 + 2 * S_BUFSZ)     // 224256

__global__ void __launch_bounds__(NTHR, 1)
ldconv_main_k(const float* __restrict__ x, float* __restrict__ out)
{
    extern __shared__ char smem[];
    const u32 sb = smem_u32(smem);
    const int t = threadIdx.x;
    const int wid = t >> 5;
    const int lane = t & 31;
    const int b = blockIdx.y;
    const int y = blockIdx.x;

    // ---- prologue: bilinear metadata for 128 px x 9 offsets ----
    float4*  metaw = (float4*)(smem + S_METAW);
    ushort4* metai = (ushort4*)(smem + S_METAI);
    for (int task = t; task < NP * NPX; task += NTHR) {
        int n  = task >> 7;
        int px = task & 127;
        float offr = g_offset[((b * 18 + n) * Hh + y) * Ww + px];
        float offc = g_offset[((b * 18 + NP + n) * Hh + y) * Ww + px];
        float pr = (float)y  + (float)(n / 3) + offr;
        float pc = (float)px + (float)(n % 3) + offc;

        float ltr = floorf(pr), ltc = floorf(pc);
        float rbr = ltr + 1.f,  rbc = ltc + 1.f;
        ltr = fminf(fmaxf(ltr, 0.f), 127.f);
        rbr = fminf(fmaxf(rbr, 0.f), 127.f);
        ltc = fminf(fmaxf(ltc, 0.f), 127.f);
        rbc = fminf(fmaxf(rbc, 0.f), 127.f);
        pr  = fminf(fmaxf(pr, 0.f), 127.f);
        pc  = fminf(fmaxf(pc, 0.f), 127.f);

        float dr_lt = 1.f + (ltr - pr);
        float dr_rb = 1.f - (rbr - pr);
        float dc_lt = 1.f + (ltc - pc);
        float dc_rb = 1.f - (rbc - pc);

        float4 g;
        g.x = dr_lt * dc_lt;   // lt
        g.y = dr_rb * dc_rb;   // rb
        g.z = dr_lt * dc_rb;   // lb
        g.w = dr_rb * dc_lt;   // rt
        metaw[task] = g;

        int iltr = (int)ltr, iltc = (int)ltc;
        int irbr = (int)rbr, irbc = (int)rbc;
        ushort4 iv;
        iv.x = (unsigned short)(iltr * Ww + iltc);
        iv.y = (unsigned short)(irbr * Ww + irbc);
        iv.z = (unsigned short)(iltr * Ww + irbc);
        iv.w = (unsigned short)(irbr * Ww + iltc);
        metai[task] = iv;
    }
    __syncthreads();

    const float* xb = x + (size_t)b * Cc * HW;
    const int px = t & 127;      // pixel this thread gathers for
    const int kq = t >> 7;       // k-quarter (16 k each)

    float acc[4][4][4];
#pragma unroll
    for (int i = 0; i < 4; i++)
#pragma unroll
        for (int j = 0; j < 4; j++)
#pragma unroll
            for (int q = 0; q < 4; q++) acc[i][j][q] = 0.f;

    const int bo = (wid & 3) * 64;    // warp o-base
    const int bn = (wid >> 2) * 32;   // warp px-base

    // ================= fill(tile) =================
    auto fill = [&](int tile) {
        const u32 buf = S_BUF0 + (u32)(tile & 1) * S_BUFSZ;
        // ---- A tiles ----
        {
            const uint4* sh = (const uint4*)(g_wa_hi + (size_t)tile * OUTC * BK);
            const uint4* sl = (const uint4*)(g_wa_lo + (size_t)tile * OUTC * BK);
#pragma unroll
            for (int i = 0; i < 4; i++) {
                int e  = t + i * NTHR;         // uint4 index 0..2047
                int o  = e >> 3;
                int jq = e & 7;
                u32 sw = swz((u32)(o * 128 + jq * 16));
                *(uint4*)(smem + buf + S_AH + sw) = sh[e];
                *(uint4*)(smem + buf + S_AL + sw) = sl[e];
            }
        }
        // ---- B tiles: gather + bf16 hi/lo split ----
        {
            const int kg0 = tile * BK + kq * 16;
            const int n   = kg0 >> 7;
            const int c0  = kg0 & 127;
            float4  gw = metaw[n * 128 + px];
            ushort4 gi = metai[n * 128 + px];
            const float* xc = xb + (size_t)c0 * HW;
#pragma unroll
            for (int q = 0; q < 2; q++) {
                u32 hreg[4], lreg[4];
#pragma unroll
                for (int jj = 0; jj < 4; jj++) {
                    const float* p0 = xc + (size_t)(q * 8 + jj * 2) * HW;
                    const float* p1 = p0 + HW;
                    float v0 = gw.x * __ldg(p0 + gi.x) + gw.y * __ldg(p0 + gi.y)
                             + gw.z * __ldg(p0 + gi.z) + gw.w * __ldg(p0 + gi.w);
                    float v1 = gw.x * __ldg(p1 + gi.x) + gw.y * __ldg(p1 + gi.y)
                             + gw.z * __ldg(p1 + gi.z) + gw.w * __ldg(p1 + gi.w);
                    u32 hp;
                    asm("cvt.rn.bf16x2.f32 %0, %1, %2;" : "=r"(hp) : "f"(v1), "f"(v0));
                    float r0 = v0 - __uint_as_float(hp << 16);
                    float r1 = v1 - __uint_as_float(hp & 0xFFFF0000u);
                    u32 lp;
                    asm("cvt.rn.bf16x2.f32 %0, %1, %2;" : "=r"(lp) : "f"(r1), "f"(r0));
                    hreg[jj] = hp;
                    lreg[jj] = lp;
                }
                u32 sw = swz((u32)(px * 128 + kq * 32 + q * 16));
                *(uint4*)(smem + buf + S_BH + sw) = make_uint4(hreg[0], hreg[1], hreg[2], hreg[3]);
                *(uint4*)(smem + buf + S_BL + sw) = make_uint4(lreg[0], lreg[1], lreg[2], lreg[3]);
            }
        }
    };

    // ================= compute(tile) =================
    auto compute = [&](int tile) {
        const u32 buf = sb + S_BUF0 + (u32)(tile & 1) * S_BUFSZ;
        u32 a[4][4], bh[4][2], bl[4][2];
#pragma unroll
        for (int ks = 0; ks < 4; ks++) {
            // B fragments (hi and lo)
#pragma unroll
            for (int j = 0; j < 2; j++) {
                int nrow = bn + j * 16 + (lane & 7) + ((lane >> 4) << 3);
                int kb   = ks * 32 + ((lane >> 3) & 1) * 16;
                u32 sw = swz((u32)(nrow * 128 + kb));
                ldsm_x4(bh[2*j][0], bh[2*j][1], bh[2*j+1][0], bh[2*j+1][1], buf + S_BH + sw);
                ldsm_x4(bl[2*j][0], bl[2*j][1], bl[2*j+1][0], bl[2*j+1][1], buf + S_BL + sw);
            }
            // A-hi fragments
#pragma unroll
            for (int mi = 0; mi < 4; mi++) {
                int ar = bo + mi * 16 + (lane & 15);
                int kb = ks * 32 + (lane >> 4) * 16;
                u32 sw = swz((u32)(ar * 128 + kb));
                ldsm_x4(a[mi][0], a[mi][1], a[mi][2], a[mi][3], buf + S_AH + sw);
            }
            // hi*hi and hi*lo
#pragma unroll
            for (int mi = 0; mi < 4; mi++)
#pragma unroll
                for (int nt = 0; nt < 4; nt++) {
                    mma_bf16(acc[mi][nt], a[mi], bh[nt]);
                    mma_bf16(acc[mi][nt], a[mi], bl[nt]);
                }
            // A-lo fragments (overwrite)
#pragma unroll
            for (int mi = 0; mi < 4; mi++) {
                int ar = bo + mi * 16 + (lane & 15);
                int kb = ks * 32 + (lane >> 4) * 16;
                u32 sw = swz((u32)(ar * 128 + kb));
                ldsm_x4(a[mi][0], a[mi][1], a[mi][2], a[mi][3], buf + S_AL + sw);
            }
            // lo*hi
#pragma unroll
            for (int mi = 0; mi < 4; mi++)
#pragma unroll
                for (int nt = 0; nt < 4; nt++)
                    mma_bf16(acc[mi][nt], a[mi], bh[nt]);
        }
    };

    // ================= pipeline =================
    fill(0);
    __syncthreads();
    for (int tile = 0; tile < NT; tile++) {
        compute(tile);
        if (tile < NT - 1) fill(tile + 1);
        __syncthreads();
    }

    // ---- epilogue: accs -> out ----
    const int g  = lane >> 2;
    const int tg = lane & 3;
#pragma unroll
    for (int mi = 0; mi < 4; mi++) {
#pragma unroll
        for (int nt = 0; nt < 4; nt++) {
            int pxo = bn + nt * 8 + 2 * tg;
            int o0  = bo + mi * 16 + g;
            int o1  = o0 + 8;
            float* base = out + (size_t)b * OUTC * HW + y * Ww + pxo;
            *(float2*)(base + (size_t)o0 * HW) = make_float2(acc[mi][nt][0], acc[mi][nt][1]);
            *(float2*)(base + (size_t)o1 * HW) = make_float2(acc[mi][nt][2], acc[mi][nt][3]);
        }
    }
}

// ======================================================================
// launch
// ======================================================================
extern "C" void kernel_launch(void* const* d_in, const int* in_sizes, int n_in,
                              void* d_out, int out_size)
{
    const float* x  = nullptr;   // 8388608
    const float* wp = nullptr;   // 20736
    const float* bp = nullptr;   // 18
    const float* wc = nullptr;   // 294912
    for (int i = 0; i < n_in; i++) {
        switch (in_sizes[i]) {
            case 8388608: x  = (const float*)d_in[i]; break;
            case 20736:   wp = (const float*)d_in[i]; break;
            case 18:      bp = (const float*)d_in[i]; break;
            case 294912:  wc = (const float*)d_in[i]; break;
            default: break;
        }
    }
    if (!x)  x  = (const float*)d_in[0];
    if (!wp) wp = (const float*)d_in[1];
    if (!bp) bp = (const float*)d_in[2];
    if (!wc) wc = (const float*)d_in[3];

    float* out = (float*)d_out;

    static bool attr_set = false;
    if (!attr_set) {
        cudaFuncSetAttribute(ldconv_main_k,
                             cudaFuncAttributeMaxDynamicSharedMemorySize, S_TOTAL);
        attr_set = true;
    }

    wtrans_k<<<(NT * OUTC * BK + 255) / 256, 256>>>(wc);
    offset_conv_k<<<dim3(Hh / 2, Bb), 128>>>(x, wp, bp);
    ldconv_main_k<<<dim3(Hh, Bb), NTHR, S_TOTAL>>>(x, out);
}

// round 7
// speedup vs baseline: 1.7665x; 1.1157x over previous
#include <cuda_runtime.h>
#include <cuda_bf16.h>
#include <cstdint>

#define Hh   128
#define Ww   128
#define HW   16384
#define Cc   128
#define NP   9
#define OUTC 256
#define Bb   4
#define BK   64
#define NT   18          // K tiles (K = 1152)
#define NPX  128         // pixels per CTA (one image row)
#define NTHR 512

typedef unsigned long long ull;
typedef unsigned int u32;

// -------- device scratch --------
__device__ float g_offset[Bb * 2 * NP * HW];            // (b, 18, H, W)
__device__ __nv_bfloat16 g_wa_hi[NT * OUTC * BK];       // [tile][o][j]
__device__ __nv_bfloat16 g_wa_lo[NT * OUTC * BK];

// ---------------- helpers ----------------
__device__ __forceinline__ u32 smem_u32(const void* p) {
    u32 a;
    asm("{ .reg .u64 t; cvta.to.shared.u64 t, %1; cvt.u32.u64 %0, t; }" : "=r"(a) : "l"(p));
    return a;
}
__device__ __forceinline__ void ldsm_x4(u32& r0, u32& r1, u32& r2, u32& r3, u32 addr) {
    asm volatile("ldmatrix.sync.aligned.m8n8.x4.shared.b16 {%0,%1,%2,%3}, [%4];"
                 : "=r"(r0), "=r"(r1), "=r"(r2), "=r"(r3) : "r"(addr));
}
__device__ __forceinline__ void mma_bf16(float* d, const u32* a, const u32* b) {
    asm("mma.sync.aligned.m16n8k16.row.col.f32.bf16.bf16.f32 "
        "{%0,%1,%2,%3},{%4,%5,%6,%7},{%8,%9},{%0,%1,%2,%3};"
        : "+f"(d[0]), "+f"(d[1]), "+f"(d[2]), "+f"(d[3])
        : "r"(a[0]), "r"(a[1]), "r"(a[2]), "r"(a[3]), "r"(b[0]), "r"(b[1]));
}
__device__ __forceinline__ u32 swz(u32 off) { return off ^ ((off >> 3) & 0x70); }

__device__ __forceinline__ void cp_async16(u32 dst, const void* src) {
    asm volatile("cp.async.cg.shared.global [%0], [%1], 16;" :: "r"(dst), "l"(src));
}
#define CP_COMMIT() asm volatile("cp.async.commit_group;" ::: "memory")
#define CP_WAIT0()  asm volatile("cp.async.wait_group 0;" ::: "memory")

// packed f32x2 helpers (offset conv)
__device__ __forceinline__ void ffma2(ull& d, ull a, ull b) {
    asm("fma.rn.f32x2 %0, %1, %2, %0;" : "+l"(d) : "l"(a), "l"(b));
}
__device__ __forceinline__ ull pack2(float lo, float hi) {
    ull r; asm("mov.b64 %0, {%1, %2};" : "=l"(r) : "f"(lo), "f"(hi)); return r;
}
__device__ __forceinline__ float2 unpack2(ull v) {
    float2 f; asm("mov.b64 {%0, %1}, %2;" : "=f"(f.x), "=f"(f.y) : "l"(v)); return f;
}

// ======================================================================
// Kernel 1: w_conv (outc, C, N, 1) -> tiled bf16 hi/lo A: [tile][o][j]
// ======================================================================
__global__ void wtrans_k(const float* __restrict__ wc) {
    int i = blockIdx.x * 256 + threadIdx.x;
    if (i < NT * OUTC * BK) {
        int j = i & 63;
        int o = (i >> 6) & 255;
        int tt = i >> 14;
        int k = tt * 64 + j;
        int n = k >> 7;
        int c = k & 127;
        float w = wc[(o * Cc + c) * NP + n];
        __nv_bfloat16 h = __float2bfloat16_rn(w);
        float hf = __bfloat162float(h);
        __nv_bfloat16 l = __float2bfloat16_rn(w - hf);
        g_wa_hi[i] = h;
        g_wa_lo[i] = l;
    }
}

// ======================================================================
// Kernel 2: offset conv (proven, unchanged)
// ======================================================================
__global__ void __launch_bounds__(128) offset_conv_k(
    const float* __restrict__ x,
    const float* __restrict__ wp,
    const float* __restrict__ bp)
{
    const int y0 = blockIdx.x * 2;
    const int b  = blockIdx.y;
    const int tx = threadIdx.x;

    __shared__ float xr[4][132];
    __shared__ float ws2[9][18];

    ull acc0[9], acc1[9];
#pragma unroll
    for (int p = 0; p < 9; p++) { acc0[p] = 0ULL; acc1[p] = 0ULL; }

    const float* xb = x + (size_t)b * Cc * HW;

    for (int c = 0; c < Cc; c++) {
        __syncthreads();
        for (int i = tx; i < 162; i += 128) {
            int k  = i / 18;
            int ch = i % 18;
            ws2[k][ch] = wp[ch * (Cc * 9) + c * 9 + k];
        }
        for (int i = tx; i < 4 * 132; i += 128) {
            int r  = i / 132;
            int cc = i % 132;
            int yy = y0 + r - 1;
            int xx = cc - 1;
            float v = 0.f;
            if (yy >= 0 && yy < Hh && xx >= 0 && xx < Ww)
                v = xb[c * HW + yy * Ww + xx];
            xr[r][cc] = v;
        }
        __syncthreads();

#pragma unroll
        for (int k = 0; k < 9; k++) {
            const int ky = k / 3, kx = k % 3;
            float xv0 = xr[ky][tx + kx];
            float xv1 = xr[ky + 1][tx + kx];
            ull x0d = pack2(xv0, xv0);
            ull x1d = pack2(xv1, xv1);
            const ull* wrow = (const ull*)&ws2[k][0];
#pragma unroll
            for (int p = 0; p < 9; p++) {
                ull wpair = wrow[p];
                ffma2(acc0[p], wpair, x0d);
                ffma2(acc1[p], wpair, x1d);
            }
        }
    }

#pragma unroll
    for (int p = 0; p < 9; p++) {
        float2 a0 = unpack2(acc0[p]);
        float2 a1 = unpack2(acc1[p]);
        int ch0 = 2 * p, ch1 = 2 * p + 1;
        float b0 = bp[ch0], b1 = bp[ch1];
        g_offset[((b * 18 + ch0) * Hh + y0) * Ww + tx]     = a0.x + b0;
        g_offset[((b * 18 + ch1) * Hh + y0) * Ww + tx]     = a0.y + b1;
        g_offset[((b * 18 + ch0) * Hh + y0 + 1) * Ww + tx] = a1.x + b0;
        g_offset[((b * 18 + ch1) * Hh + y0 + 1) * Ww + tx] = a1.y + b1;
    }
}

// ======================================================================
// Kernel 3: fused gather + warp-MMA bf16 3-split GEMM, pipelined:
//   - A tiles prefetched with cp.async (no register staging)
//   - B gather for tile+1 interleaved into the 4 MMA k-steps of tile
// CTA = (batch b, row y): out[b, 0..255, y, 0..127]; 512 thr = 16 warps.
// ======================================================================
#define S_METAW 0                          // float4[1152]  -> 18432
#define S_METAI 18432                      // ushort4[1152] ->  9216
#define S_BUF0  27648
#define S_BUFSZ 98304
#define S_AH 0
#define S_AL 32768
#define S_BH 65536
#define S_BL 81920
#define S_TOTAL (S_BUF0 + 2 * S_BUFSZ)     // 224256

__global__ void __launch_bounds__(NTHR, 1)
ldconv_main_k(const float* __restrict__ x, float* __restrict__ out)
{
    extern __shared__ char smem[];
    const u32 sb = smem_u32(smem);
    const int t = threadIdx.x;
    const int wid = t >> 5;
    const int lane = t & 31;
    const int b = blockIdx.y;
    const int y = blockIdx.x;

    // ---- prologue: bilinear metadata for 128 px x 9 offsets ----
    float4*  metaw = (float4*)(smem + S_METAW);
    ushort4* metai = (ushort4*)(smem + S_METAI);
    for (int task = t; task < NP * NPX; task += NTHR) {
        int n  = task >> 7;
        int px = task & 127;
        float offr = g_offset[((b * 18 + n) * Hh + y) * Ww + px];
        float offc = g_offset[((b * 18 + NP + n) * Hh + y) * Ww + px];
        float pr = (float)y  + (float)(n / 3) + offr;
        float pc = (float)px + (float)(n % 3) + offc;

        float ltr = floorf(pr), ltc = floorf(pc);
        float rbr = ltr + 1.f,  rbc = ltc + 1.f;
        ltr = fminf(fmaxf(ltr, 0.f), 127.f);
        rbr = fminf(fmaxf(rbr, 0.f), 127.f);
        ltc = fminf(fmaxf(ltc, 0.f), 127.f);
        rbc = fminf(fmaxf(rbc, 0.f), 127.f);
        pr  = fminf(fmaxf(pr, 0.f), 127.f);
        pc  = fminf(fmaxf(pc, 0.f), 127.f);

        float dr_lt = 1.f + (ltr - pr);
        float dr_rb = 1.f - (rbr - pr);
        float dc_lt = 1.f + (ltc - pc);
        float dc_rb = 1.f - (rbc - pc);

        float4 g;
        g.x = dr_lt * dc_lt;
        g.y = dr_rb * dc_rb;
        g.z = dr_lt * dc_rb;
        g.w = dr_rb * dc_lt;
        metaw[task] = g;

        int iltr = (int)ltr, iltc = (int)ltc;
        int irbr = (int)rbr, irbc = (int)rbc;
        ushort4 iv;
        iv.x = (unsigned short)(iltr * Ww + iltc);
        iv.y = (unsigned short)(irbr * Ww + irbc);
        iv.z = (unsigned short)(iltr * Ww + irbc);
        iv.w = (unsigned short)(irbr * Ww + iltc);
        metai[task] = iv;
    }
    __syncthreads();

    const float* xb = x + (size_t)b * Cc * HW;
    const int px = t & 127;      // pixel this thread gathers for
    const int kq = t >> 7;       // k-quarter (16 k each)

    float acc[4][4][4];
#pragma unroll
    for (int i = 0; i < 4; i++)
#pragma unroll
        for (int j = 0; j < 4; j++)
#pragma unroll
            for (int q = 0; q < 4; q++) acc[i][j][q] = 0.f;

    const int bo = (wid & 3) * 64;    // warp o-base
    const int bn = (wid >> 2) * 32;   // warp px-base

    // ---- async A fill ----
    auto fillA_async = [&](int tile) {
        const u32 dst = sb + S_BUF0 + (u32)(tile & 1) * S_BUFSZ;
        const uint4* sh = (const uint4*)(g_wa_hi + (size_t)tile * OUTC * BK);
        const uint4* sl = (const uint4*)(g_wa_lo + (size_t)tile * OUTC * BK);
#pragma unroll
        for (int i = 0; i < 4; i++) {
            int e  = t + i * NTHR;
            int o  = e >> 3;
            int jq = e & 7;
            u32 sw = swz((u32)(o * 128 + jq * 16));
            cp_async16(dst + S_AH + sw, sh + e);
            cp_async16(dst + S_AL + sw, sl + e);
        }
        CP_COMMIT();
    };

    // ---- full synchronous B gather (prologue only) ----
    auto gatherB_full = [&](int tile) {
        const u32 bufo = S_BUF0 + (u32)(tile & 1) * S_BUFSZ;
        const int kg0 = tile * BK + kq * 16;
        const int n   = kg0 >> 7;
        const int c0  = kg0 & 127;
        float4  gw = metaw[n * 128 + px];
        ushort4 gi = metai[n * 128 + px];
        const float* xc = xb + (size_t)c0 * HW;
#pragma unroll
        for (int q = 0; q < 2; q++) {
            u32 hreg[4], lreg[4];
#pragma unroll
            for (int jj = 0; jj < 4; jj++) {
                const float* p0 = xc + (size_t)(q * 8 + jj * 2) * HW;
                const float* p1 = p0 + HW;
                float v0 = gw.x * __ldg(p0 + gi.x) + gw.y * __ldg(p0 + gi.y)
                         + gw.z * __ldg(p0 + gi.z) + gw.w * __ldg(p0 + gi.w);
                float v1 = gw.x * __ldg(p1 + gi.x) + gw.y * __ldg(p1 + gi.y)
                         + gw.z * __ldg(p1 + gi.z) + gw.w * __ldg(p1 + gi.w);
                u32 hp;
                asm("cvt.rn.bf16x2.f32 %0, %1, %2;" : "=r"(hp) : "f"(v1), "f"(v0));
                float r0 = v0 - __uint_as_float(hp << 16);
                float r1 = v1 - __uint_as_float(hp & 0xFFFF0000u);
                u32 lp;
                asm("cvt.rn.bf16x2.f32 %0, %1, %2;" : "=r"(lp) : "f"(r1), "f"(r0));
                hreg[jj] = hp;
                lreg[jj] = lp;
            }
            u32 sw = swz((u32)(px * 128 + kq * 32 + q * 16));
            *(uint4*)(smem + bufo + S_BH + sw) = make_uint4(hreg[0], hreg[1], hreg[2], hreg[3]);
            *(uint4*)(smem + bufo + S_BL + sw) = make_uint4(lreg[0], lreg[1], lreg[2], lreg[3]);
        }
    };

    // ---- compute(tile) with interleaved gather for tile+1 ----
    auto compute = [&](int tile, bool gnext) {
        const u32 buf  = sb + S_BUF0 + (u32)(tile & 1) * S_BUFSZ;
        const u32 nbufo = S_BUF0 + (u32)((tile + 1) & 1) * S_BUFSZ;

        // gather metadata for tile+1
        float4  gw;
        ushort4 gi;
        const float* xc = xb;
        if (gnext) {
            const int kg0 = (tile + 1) * BK + kq * 16;
            const int n   = kg0 >> 7;
            const int c0  = kg0 & 127;
            gw = metaw[n * 128 + px];
            gi = metai[n * 128 + px];
            xc = xb + (size_t)c0 * HW;
        }

        u32 a[4][4], bh[4][2], bl[4][2];
#pragma unroll
        for (int ks = 0; ks < 4; ks++) {
            // ---- issue 16 gather LDGs for unit ks (q = ks>>1, jp = ks&1) ----
            float gvA0[4], gvA1[4], gvB0[4], gvB1[4];
            if (gnext) {
                const int q = ks >> 1, jp = ks & 1;
                const float* pA0 = xc + (size_t)(q * 8 + jp * 4 + 0) * HW;
                const float* pA1 = pA0 + HW;
                const float* pB0 = xc + (size_t)(q * 8 + jp * 4 + 2) * HW;
                const float* pB1 = pB0 + HW;
                gvA0[0] = __ldg(pA0 + gi.x); gvA0[1] = __ldg(pA0 + gi.y);
                gvA0[2] = __ldg(pA0 + gi.z); gvA0[3] = __ldg(pA0 + gi.w);
                gvA1[0] = __ldg(pA1 + gi.x); gvA1[1] = __ldg(pA1 + gi.y);
                gvA1[2] = __ldg(pA1 + gi.z); gvA1[3] = __ldg(pA1 + gi.w);
                gvB0[0] = __ldg(pB0 + gi.x); gvB0[1] = __ldg(pB0 + gi.y);
                gvB0[2] = __ldg(pB0 + gi.z); gvB0[3] = __ldg(pB0 + gi.w);
                gvB1[0] = __ldg(pB1 + gi.x); gvB1[1] = __ldg(pB1 + gi.y);
                gvB1[2] = __ldg(pB1 + gi.z); gvB1[3] = __ldg(pB1 + gi.w);
            }

            // ---- B fragments (hi and lo) ----
#pragma unroll
            for (int j = 0; j < 2; j++) {
                int nrow = bn + j * 16 + (lane & 7) + ((lane >> 4) << 3);
                int kb   = ks * 32 + ((lane >> 3) & 1) * 16;
                u32 sw = swz((u32)(nrow * 128 + kb));
                ldsm_x4(bh[2*j][0], bh[2*j][1], bh[2*j+1][0], bh[2*j+1][1], buf + S_BH + sw);
                ldsm_x4(bl[2*j][0], bl[2*j][1], bl[2*j+1][0], bl[2*j+1][1], buf + S_BL + sw);
            }
            // ---- A-hi fragments ----
#pragma unroll
            for (int mi = 0; mi < 4; mi++) {
                int ar = bo + mi * 16 + (lane & 15);
                int kb = ks * 32 + (lane >> 4) * 16;
                u32 sw = swz((u32)(ar * 128 + kb));
                ldsm_x4(a[mi][0], a[mi][1], a[mi][2], a[mi][3], buf + S_AH + sw);
            }
            // hi*hi and hi*lo
#pragma unroll
            for (int mi = 0; mi < 4; mi++)
#pragma unroll
                for (int nt = 0; nt < 4; nt++) {
                    mma_bf16(acc[mi][nt], a[mi], bh[nt]);
                    mma_bf16(acc[mi][nt], a[mi], bl[nt]);
                }
            // ---- A-lo fragments (overwrite) ----
#pragma unroll
            for (int mi = 0; mi < 4; mi++) {
                int ar = bo + mi * 16 + (lane & 15);
                int kb = ks * 32 + (lane >> 4) * 16;
                u32 sw = swz((u32)(ar * 128 + kb));
                ldsm_x4(a[mi][0], a[mi][1], a[mi][2], a[mi][3], buf + S_AL + sw);
            }
            // lo*hi
#pragma unroll
            for (int mi = 0; mi < 4; mi++)
#pragma unroll
                for (int nt = 0; nt < 4; nt++)
                    mma_bf16(acc[mi][nt], a[mi], bh[nt]);

            // ---- finish gather unit ks: combine, split, store ----
            if (gnext) {
                const int q = ks >> 1, jp = ks & 1;
                float v0a = gw.x * gvA0[0] + gw.y * gvA0[1] + gw.z * gvA0[2] + gw.w * gvA0[3];
                float v1a = gw.x * gvA1[0] + gw.y * gvA1[1] + gw.z * gvA1[2] + gw.w * gvA1[3];
                float v0b = gw.x * gvB0[0] + gw.y * gvB0[1] + gw.z * gvB0[2] + gw.w * gvB0[3];
                float v1b = gw.x * gvB1[0] + gw.y * gvB1[1] + gw.z * gvB1[2] + gw.w * gvB1[3];
                u32 hpa, hpb;
                asm("cvt.rn.bf16x2.f32 %0, %1, %2;" : "=r"(hpa) : "f"(v1a), "f"(v0a));
                asm("cvt.rn.bf16x2.f32 %0, %1, %2;" : "=r"(hpb) : "f"(v1b), "f"(v0b));
                float r0a = v0a - __uint_as_float(hpa << 16);
                float r1a = v1a - __uint_as_float(hpa & 0xFFFF0000u);
                float r0b = v0b - __uint_as_float(hpb << 16);
                float r1b = v1b - __uint_as_float(hpb & 0xFFFF0000u);
                u32 lpa, lpb;
                asm("cvt.rn.bf16x2.f32 %0, %1, %2;" : "=r"(lpa) : "f"(r1a), "f"(r0a));
                asm("cvt.rn.bf16x2.f32 %0, %1, %2;" : "=r"(lpb) : "f"(r1b), "f"(r0b));
                u32 sw = swz((u32)(px * 128 + kq * 32 + q * 16 + jp * 8));
                *(uint2*)(smem + nbufo + S_BH + sw) = make_uint2(hpa, hpb);
                *(uint2*)(smem + nbufo + S_BL + sw) = make_uint2(lpa, lpb);
            }
        }
    };

    // ================= pipeline =================
    fillA_async(0);
    gatherB_full(0);
    CP_WAIT0();
    __syncthreads();

    for (int tile = 0; tile < NT; tile++) {
        if (tile + 1 < NT) fillA_async(tile + 1);
        compute(tile, tile + 1 < NT);
        CP_WAIT0();
        __syncthreads();
    }

    // ---- epilogue: accs -> out ----
    const int g  = lane >> 2;
    const int tg = lane & 3;
#pragma unroll
    for (int mi = 0; mi < 4; mi++) {
#pragma unroll
        for (int nt = 0; nt < 4; nt++) {
            int pxo = bn + nt * 8 + 2 * tg;
            int o0  = bo + mi * 16 + g;
            int o1  = o0 + 8;
            float* base = out + (size_t)b * OUTC * HW + y * Ww + pxo;
            *(float2*)(base + (size_t)o0 * HW) = make_float2(acc[mi][nt][0], acc[mi][nt][1]);
            *(float2*)(base + (size_t)o1 * HW) = make_float2(acc[mi][nt][2], acc[mi][nt][3]);
        }
    }
}

// ======================================================================
// launch
// ======================================================================
extern "C" void kernel_launch(void* const* d_in, const int* in_sizes, int n_in,
                              void* d_out, int out_size)
{
    const float* x  = nullptr;   // 8388608
    const float* wp = nullptr;   // 20736
    const float* bp = nullptr;   // 18
    const float* wc = nullptr;   // 294912
    for (int i = 0; i < n_in; i++) {
        switch (in_sizes[i]) {
            case 8388608: x  = (const float*)d_in[i]; break;
            case 20736:   wp = (const float*)d_in[i]; break;
            case 18:      bp = (const float*)d_in[i]; break;
            case 294912:  wc = (const float*)d_in[i]; break;
            default: break;
        }
    }
    if (!x)  x  = (const float*)d_in[0];
    if (!wp) wp = (const float*)d_in[1];
    if (!bp) bp = (const float*)d_in[2];
    if (!wc) wc = (const float*)d_in[3];

    float* out = (float*)d_out;

    cudaFuncSetAttribute(ldconv_main_k,
                         cudaFuncAttributeMaxDynamicSharedMemorySize, S_TOTAL);

    wtrans_k<<<(NT * OUTC * BK + 255) / 256, 256>>>(wc);
    offset_conv_k<<<dim3(Hh / 2, Bb), 128>>>(x, wp, bp);
    ldconv_main_k<<<dim3(Hh, Bb), NTHR, S_TOTAL>>>(x, out);
}